// round 2
// baseline (speedup 1.0000x reference)
#include <cuda_runtime.h>
#include <math.h>
#include <stdint.h>

#define H 2048
#define G 8192
#define NBQ 8
#define NBLK 148
#define NTH 448
#define NWARPS ((NBLK*NTH)/32)   // 2072 warps total

// ---------------- device state (scratch; no allocations) ----------------
__device__ float d_xproj[18][G];   // row0 = zeros, 1..9 = W_ih @ enc[0..8], 10..17 = anchor projections
__device__ float d_bsum[G];        // b_ih + b_hh
__device__ float d_c[H];
__device__ float d_hb[2][H];       // ping-pong hidden state
__device__ float d_aw1[10][H];     // anchors_w1
__device__ float d_hw2[H];         // h @ w_attn_2^T
__device__ int   d_xrow;           // dynamic xproj row index for next cell
__device__ unsigned g_count = 0;
__device__ unsigned g_flag  = 0;   // monotonic barrier generation (persists across launches)
__device__ unsigned d_k0, d_k1;    // threefry key
__device__ float d_lp, d_ent;

struct P {
  const float *enc,*wih,*bih,*whh,*bhh,*wsoft,*bsoft,*bsnl,*w1,*w2,*v;
  float* out;
};

// ---------------- grid barrier (monotonic flag, launch-safe) ----------------
__device__ __forceinline__ void gsync(unsigned &gen){
  __syncthreads();
  __threadfence();
  if (threadIdx.x == 0){
    unsigned target = gen + 1u;
    unsigned a = atomicAdd(&g_count, 1u);
    if (a == (unsigned)gridDim.x - 1u){
      g_count = 0u;
      __threadfence();
      *((volatile unsigned*)&g_flag) = target;
    } else {
      while (*((volatile unsigned*)&g_flag) < target) { }
    }
  }
  gen += 1u;
  __syncthreads();
  __threadfence();
}

// ---------------- threefry2x32 (20 rounds, JAX-exact) ----------------
__device__ __forceinline__ void tf2(unsigned k0, unsigned k1, unsigned x0, unsigned x1,
                                    unsigned &o0, unsigned &o1){
  unsigned ks2 = k0 ^ k1 ^ 0x1BD11BDAu;
  x0 += k0; x1 += k1;
#define RND(r) { x0 += x1; x1 = (x1<<(r))|(x1>>(32-(r))); x1 ^= x0; }
  RND(13) RND(15) RND(26) RND(6)   x0 += k1;  x1 += ks2 + 1u;
  RND(17) RND(29) RND(16) RND(24)  x0 += ks2; x1 += k0  + 2u;
  RND(13) RND(15) RND(26) RND(6)   x0 += k0;  x1 += k1  + 3u;
  RND(17) RND(29) RND(16) RND(24)  x0 += k1;  x1 += ks2 + 4u;
  RND(13) RND(15) RND(26) RND(6)   x0 += ks2; x1 += k0  + 5u;
#undef RND
  o0 = x0; o1 = x1;
}

// JAX partitionable-threefry semantics (default since jax 0.4.36):
//  split(key,2):  key_i = both output words of tf(key, hi=0, lo=i)
//  random_bits(key,(n,)): bits[i] = o0 ^ o1 of tf(key, hi=0, lo=i)
// Runs on a single thread (block 0, thread 0).
__device__ int do_sample(int n, const float* lg){
  unsigned nk0, nk1, s0, s1;
  tf2(d_k0, d_k1, 0u, 0u, nk0, nk1);   // new key
  tf2(d_k0, d_k1, 0u, 1u, s0,  s1);    // sub key
  d_k0 = nk0; d_k1 = nk1;

  const float TINY = 1.17549435e-38f;
  float best = -INFINITY; int bi = 0;
  for (int i = 0; i < n; i++){
    unsigned o0, o1;
    tf2(s0, s1, 0u, (unsigned)i, o0, o1);
    unsigned bits = o0 ^ o1;                                      // 32-bit fold
    float f = __uint_as_float((bits >> 9) | 0x3f800000u) - 1.0f;  // [0,1)
    float u = f * (1.0f - TINY) + TINY;
    u = fmaxf(TINY, u);
    float z = -logf(-logf(u)) + lg[i];   // gumbel + logit
    if (z > best){ best = z; bi = i; }
  }
  float mx = lg[0];
  for (int i = 1; i < n; i++) mx = fmaxf(mx, lg[i]);
  float se = 0.f;
  for (int i = 0; i < n; i++) se += expf(lg[i] - mx);
  float lse = logf(se);
  d_lp += -(lg[bi] - mx - lse);
  float e = 0.f;
  for (int i = 0; i < n; i++){ float ls = lg[i] - mx - lse; e -= ls * expf(ls); }
  d_ent += e;
  return bi;
}

__device__ __forceinline__ float sigf(float x){ return 1.f / (1.f + expf(-x)); }

// warp dot of one 2048-length row against smem vector
__device__ __forceinline__ float wdot(const float* __restrict__ w,
                                      const float* __restrict__ shv, int lane){
  const float4* w4 = (const float4*)w;
  const float4* h4 = (const float4*)shv;
  float a = 0.f;
#pragma unroll
  for (int t = 0; t < 16; t++){
    float4 wv = w4[lane + 32*t];
    float4 hv = h4[lane + 32*t];
    a += wv.x*hv.x; a += wv.y*hv.y; a += wv.z*hv.z; a += wv.w*hv.w;
  }
#pragma unroll
  for (int o = 16; o; o >>= 1) a += __shfl_xor_sync(0xffffffffu, a, o);
  return a;
}

__device__ __forceinline__ void load_h_smem(float* sh, const float* hsrc){
  for (int i = threadIdx.x; i < H; i += NTH) sh[i] = __ldcg(hsrc + i);
  __syncthreads();
}

// one LSTM cell: g = xproj[row] + bsum + W_hh @ h ; update c,h. 1 barrier.
__device__ void do_cell(const P& p, int xrow, int &hp, float* sh, unsigned &gen,
                        int gw, int lane){
  load_h_smem(sh, d_hb[hp]);
  int j = gw;
  if (j < H){
    const float* whh = p.whh;
    float s0 = wdot(whh + (size_t)j        * H, sh, lane);
    float s1 = wdot(whh + (size_t)(j + H)  * H, sh, lane);
    float s2 = wdot(whh + (size_t)(j + 2*H)* H, sh, lane);
    float s3 = wdot(whh + (size_t)(j + 3*H)* H, sh, lane);
    if (lane == 0){
      int xr = (xrow >= 0) ? xrow : *((volatile int*)&d_xrow);
      const float* xp = d_xproj[xr];
      float gi = s0 + __ldcg(xp + j)       + d_bsum[j];
      float gf = s1 + __ldcg(xp + j + H)   + d_bsum[j + H];
      float gg = s2 + __ldcg(xp + j + 2*H) + d_bsum[j + 2*H];
      float go = s3 + __ldcg(xp + j + 3*H) + d_bsum[j + 3*H];
      float c2 = sigf(gf) * d_c[j] + sigf(gi) * tanhf(gg);
      float h2 = sigf(go) * tanhf(c2);
      d_c[j] = c2;
      d_hb[hp ^ 1][j] = h2;
    }
  }
  hp ^= 1;
  gsync(gen);
}

// hw2 = h @ w_attn_2^T
__device__ void do_hw2(const P& p, int hp, float* sh, unsigned &gen, int gw, int lane){
  load_h_smem(sh, d_hb[hp]);
  if (gw < H){
    float s = wdot(p.w2 + (size_t)gw * H, sh, lane);
    if (lane == 0) d_hw2[gw] = s;
  }
  gsync(gen);
}

// anchor projection (W_ih @ h -> xproj[arow]) fused with aw1[aidx] = h @ w_attn_1^T
__device__ void do_proj(const P& p, int hp, int arow, int aidx, float* sh, unsigned &gen,
                        int gw, int lane){
  load_h_smem(sh, d_hb[hp]);
  int total = (arow >= 0) ? (G + H) : H;
  for (int r = gw; r < total; r += NWARPS){
    if (arow >= 0 && r < G){
      float s = wdot(p.wih + (size_t)r * H, sh, lane);
      if (lane == 0) d_xproj[arow][r] = s;
    } else {
      int rr = (arow >= 0) ? r - G : r;
      float s = wdot(p.w1 + (size_t)rr * H, sh, lane);
      if (lane == 0) d_aw1[aidx][rr] = s;
    }
  }
  gsync(gen);
}

// attention logits over L anchors + categorical sample (block 0 only)
__device__ void do_idx_sample(const P& p, int L, int arcpos, float* sh, unsigned &gen,
                              float* out){
  if (blockIdx.x == 0){
    int wi = threadIdx.x >> 5, lane = threadIdx.x & 31;
    if (wi < L){
      float a = 0.f;
      for (int t = lane; t < H; t += 32)
        a += tanhf(__ldcg(&d_aw1[wi][t]) + __ldcg(&d_hw2[t])) * p.v[t];
#pragma unroll
      for (int o = 16; o; o >>= 1) a += __shfl_xor_sync(0xffffffffu, a, o);
      if (lane == 0) sh[wi] = a;
    }
    __syncthreads();
    if (threadIdx.x == 0){
      float lg[10];
      for (int i = 0; i < L; i++) lg[i] = 2.5f * tanhf(sh[i] / 5.0f);
      int idx = do_sample(L, lg);
      d_xrow = (idx < 2) ? 0 : (10 + idx - 2);   // zero anchors -> row 0
      out[arcpos] = (float)idx;
    }
  }
  gsync(gen);
}

// op logits = h @ w_soft^T + b_soft, tanh-squash, optional fixed bias, sample
__device__ void do_op_sample(const P& p, int hp, int use_bias, int arcpos, float* sh,
                             unsigned &gen, float* out){
  if (blockIdx.x == 0){
    int wi = threadIdx.x >> 5, lane = threadIdx.x & 31;
    if (wi < NBQ){
      const float* hc = d_hb[hp];
      float a = 0.f;
      for (int t = lane; t < H; t += 32) a += p.wsoft[wi * H + t] * __ldcg(hc + t);
#pragma unroll
      for (int o = 16; o; o >>= 1) a += __shfl_xor_sync(0xffffffffu, a, o);
      if (lane == 0) sh[wi] = a;
    }
    __syncthreads();
    if (threadIdx.x == 0){
      float lg[NBQ];
      for (int i = 0; i < NBQ; i++){
        lg[i] = tanhf((sh[i] + p.bsoft[i]) / 5.0f);   // (TANH_C/OP_RED) == 1.0
        if (use_bias) lg[i] += p.bsnl[i];
      }
      int op = do_sample(NBQ, lg);
      d_xrow = 2 + op;               // encoder_w[op+1] -> table row op+2
      out[arcpos] = (float)op;
    }
  }
  gsync(gen);
}

__global__ void __launch_bounds__(NTH, 1) ctrl_kernel(P p){
  extern __shared__ float sh[];
  unsigned gen = *((volatile unsigned*)&g_flag);
  int tid  = threadIdx.x;
  int gw   = (blockIdx.x * NTH + tid) >> 5;
  int lane = tid & 31;

  // ---- phase 0: init state + bsum + encoder projections ----
  for (int i = blockIdx.x*NTH + tid; i < H; i += NBLK*NTH){
    d_c[i] = 0.f; d_hb[0][i] = 0.f; d_hb[1][i] = 0.f;
  }
  for (int i = blockIdx.x*NTH + tid; i < G; i += NBLK*NTH){
    d_bsum[i] = p.bih[i] + p.bhh[i];
    d_xproj[0][i] = 0.f;
  }
  if (blockIdx.x == 0 && tid == 0){
    d_k0 = 0u; d_k1 = 42u;           // jax.random.key(42)
    d_lp = 0.f; d_ent = 0.f;
  }
  // encoder rows to smem (9 x 2048 floats)
  for (int i = tid; i < 9*H; i += NTH) sh[i] = p.enc[i];
  __syncthreads();
  for (int r = gw; r < G; r += NWARPS){
    const float4* w4 = (const float4*)(p.wih + (size_t)r * H);
    float acc[9];
#pragma unroll
    for (int e = 0; e < 9; e++) acc[e] = 0.f;
    for (int t = 0; t < 16; t++){
      float4 wv = w4[lane + 32*t];
#pragma unroll
      for (int e = 0; e < 9; e++){
        float4 xv = ((const float4*)sh)[e*512 + lane + 32*t];
        acc[e] += wv.x*xv.x; acc[e] += wv.y*xv.y; acc[e] += wv.z*xv.z; acc[e] += wv.w*xv.w;
      }
    }
    for (int e = 0; e < 9; e++){
      float a = acc[e];
#pragma unroll
      for (int o = 16; o; o >>= 1) a += __shfl_xor_sync(0xffffffffu, a, o);
      if (lane == 0) d_xproj[1 + e][r] = a;
    }
  }
  gsync(gen);

  // ---- two sampler runs ----
  int hp = 0;
  for (int smp = 0; smp < 2; smp++){
    int ab = smp * 32;
    int ub = (smp == 0);
    // 2 init cells: input = encoder_w[0] (row 1); zero anchors + aw1[0..1]
    for (int t = 0; t < 2; t++){
      do_cell(p, 1, hp, sh, gen, gw, lane);
      do_proj(p, hp, -1, t, sh, gen, gw, lane);
    }
    for (int L = 2; L <= 9; L++){
      for (int t = 0; t < 2; t++){
        do_cell(p, (t == 0) ? 1 : -1, hp, sh, gen, gw, lane);
        do_hw2(p, hp, sh, gen, gw, lane);
        do_idx_sample(p, L, ab + (L-2)*4 + (t == 0 ? 0 : 2), sh, gen, p.out);
      }
      for (int t = 0; t < 2; t++){
        do_cell(p, -1, hp, sh, gen, gw, lane);
        do_op_sample(p, hp, ub, ab + (L-2)*4 + (t == 0 ? 1 : 3), sh, gen, p.out);
      }
      do_cell(p, -1, hp, sh, gen, gw, lane);               // anchor cell
      do_proj(p, hp, 10 + (L-2), L, sh, gen, gw, lane);    // anchor proj + aw1[L]
    }
  }

  if (blockIdx.x == 0 && tid == 0){
    p.out[64] = d_lp;   // lp1 + lp2
    p.out[65] = d_ent;  // e1 + e2
  }
}

extern "C" void kernel_launch(void* const* d_in, const int* in_sizes, int n_in,
                              void* d_out, int out_size){
  P p;
  p.enc   = (const float*)d_in[0];
  p.wih   = (const float*)d_in[1];
  p.bih   = (const float*)d_in[2];
  p.whh   = (const float*)d_in[3];
  p.bhh   = (const float*)d_in[4];
  p.wsoft = (const float*)d_in[5];
  p.bsoft = (const float*)d_in[6];
  p.bsnl  = (const float*)d_in[7];
  p.w1    = (const float*)d_in[8];
  p.w2    = (const float*)d_in[9];
  p.v     = (const float*)d_in[10];
  p.out   = (float*)d_out;
  (void)in_sizes; (void)n_in; (void)out_size;

  size_t smem = 9 * H * sizeof(float);  // 73728 B
  cudaFuncSetAttribute(ctrl_kernel, cudaFuncAttributeMaxDynamicSharedMemorySize, (int)smem);
  ctrl_kernel<<<NBLK, NTH, smem>>>(p);
}